// round 1
// baseline (speedup 1.0000x reference)
#include <cuda_runtime.h>
#include <cuda_bf16.h>
#include <math.h>

#define N_ROWS 16384
#define NF     39
#define VP1    100001
#define NE     16
#define ND     624   // F*E
#define NH     400
#define EPS    1e-5f

// ---------------- scratch (static __device__, no allocations) ----------------
__device__ float g_deep[(size_t)N_ROWS * ND];   // 40.9 MB
__device__ float g_Z1  [(size_t)N_ROWS * NH];   // 26.2 MB
__device__ float g_Z2  [(size_t)N_ROWS * NH];   // 26.2 MB
__device__ float g_stats[4 * NH];               // sum1, sumsq1, sum2, sumsq2
__device__ float g_coef [3 * NH + 1];           // alpha1[400], beta1[400], a2[400], C

// ---------------- zero stats ----------------
__global__ void zero_kernel(float* stats) {
    int i = blockIdx.x * blockDim.x + threadIdx.x;
    if (i < 4 * NH) stats[i] = 0.f;
}

// ---------------- embedding gather + e1 + FM2 + deep ----------------
__global__ void __launch_bounds__(640) embed_kernel(
    const int* __restrict__ xi, const float* __restrict__ xv,
    const float* __restrict__ emb1, const float* __restrict__ emb2,
    const float* __restrict__ bias, float* __restrict__ deep,
    float* __restrict__ out)
{
    int n = blockIdx.x;
    int t = threadIdx.x;
    __shared__ int   idx_s[NF];
    __shared__ float xv_s[NF];
    __shared__ float vals[ND];
    __shared__ float e1s[NF];
    __shared__ float fm2s[NE];

    if (t < NF) {
        idx_s[t] = xi[n * NF + t];
        xv_s[t]  = xv[n * NF + t];
    }
    __syncthreads();

    if (t < ND) {
        int f = t >> 4, e = t & 15;
        size_t off = ((size_t)f * VP1 + idx_s[f]) * NE + e;
        float v = emb2[off] * xv_s[f];
        vals[t] = v;
        deep[(size_t)n * ND + t] = v;
    }
    if (t < NF) {
        e1s[t] = emb1[(size_t)t * VP1 + idx_s[t]] * xv_s[t];
    }
    __syncthreads();

    if (t < NE) {
        float s = 0.f, sq = 0.f;
        #pragma unroll
        for (int f = 0; f < NF; f++) {
            float v = vals[f * NE + t];
            s += v; sq += v * v;
        }
        fm2s[t] = 0.5f * (s * s - sq);
    }
    __syncthreads();

    if (t == 0) {
        float tot = bias[0];
        #pragma unroll
        for (int i = 0; i < NF; i++) tot += e1s[i];
        #pragma unroll
        for (int i = 0; i < NE; i++) tot += fm2s[i];
        out[n] = tot;
    }
}

// ---------------- fp32 SGEMM: C = op(A) @ B + bias ----------------
// op(A)[m,k] = AFFINE ? A[m,k]*alpha[k] + beta[k] : A[m,k]
// BM=128, BN=64, BK=16, 128 threads, 8x8 microtile.
template<bool AFFINE>
__global__ void __launch_bounds__(128) sgemm_kernel(
    const float* __restrict__ A, const float* __restrict__ B,
    const float* __restrict__ bias, float* __restrict__ C,
    int M, int N, int K,
    const float* __restrict__ alpha, const float* __restrict__ beta)
{
    const int BM = 128, BN = 64, BK = 16;
    __shared__ float As[BK][BM];
    __shared__ float Bs[BK][BN];

    int tid = threadIdx.x;
    int n0 = blockIdx.x * BN;
    int m0 = blockIdx.y * BM;
    int tx = tid & 7;        // 8 groups along N, TN=8
    int ty = tid >> 3;       // 16 groups along M, TM=8

    float acc[8][8];
    #pragma unroll
    for (int i = 0; i < 8; i++)
        #pragma unroll
        for (int j = 0; j < 8; j++) acc[i][j] = 0.f;

    for (int k0 = 0; k0 < K; k0 += BK) {
        // Load A tile: 2048 floats = 512 float4, 4 per thread
        #pragma unroll
        for (int l = 0; l < 4; l++) {
            int i4 = tid + l * 128;
            int m  = i4 >> 2;
            int kk = (i4 & 3) * 4;
            float4 v = *reinterpret_cast<const float4*>(
                &A[(size_t)(m0 + m) * K + k0 + kk]);
            if (AFFINE) {
                v.x = v.x * alpha[k0 + kk + 0] + beta[k0 + kk + 0];
                v.y = v.y * alpha[k0 + kk + 1] + beta[k0 + kk + 1];
                v.z = v.z * alpha[k0 + kk + 2] + beta[k0 + kk + 2];
                v.w = v.w * alpha[k0 + kk + 3] + beta[k0 + kk + 3];
            }
            As[kk + 0][m] = v.x;
            As[kk + 1][m] = v.y;
            As[kk + 2][m] = v.z;
            As[kk + 3][m] = v.w;
        }
        // Load B tile: 1024 floats = 256 float4, 2 per thread
        #pragma unroll
        for (int l = 0; l < 2; l++) {
            int i4 = tid + l * 128;
            int k  = i4 >> 4;
            int nn = (i4 & 15) * 4;
            float4 v = make_float4(0.f, 0.f, 0.f, 0.f);
            if (n0 + nn < N)
                v = *reinterpret_cast<const float4*>(
                    &B[(size_t)(k0 + k) * N + n0 + nn]);
            *reinterpret_cast<float4*>(&Bs[k][nn]) = v;
        }
        __syncthreads();

        #pragma unroll
        for (int k = 0; k < BK; k++) {
            float ra[8], rb[8];
            float4 a0 = *reinterpret_cast<const float4*>(&As[k][ty * 8]);
            float4 a1 = *reinterpret_cast<const float4*>(&As[k][ty * 8 + 4]);
            float4 b0 = *reinterpret_cast<const float4*>(&Bs[k][tx * 8]);
            float4 b1 = *reinterpret_cast<const float4*>(&Bs[k][tx * 8 + 4]);
            ra[0]=a0.x; ra[1]=a0.y; ra[2]=a0.z; ra[3]=a0.w;
            ra[4]=a1.x; ra[5]=a1.y; ra[6]=a1.z; ra[7]=a1.w;
            rb[0]=b0.x; rb[1]=b0.y; rb[2]=b0.z; rb[3]=b0.w;
            rb[4]=b1.x; rb[5]=b1.y; rb[6]=b1.z; rb[7]=b1.w;
            #pragma unroll
            for (int i = 0; i < 8; i++)
                #pragma unroll
                for (int j = 0; j < 8; j++)
                    acc[i][j] = fmaf(ra[i], rb[j], acc[i][j]);
        }
        __syncthreads();
    }

    #pragma unroll
    for (int i = 0; i < 8; i++) {
        int m = m0 + ty * 8 + i;
        #pragma unroll
        for (int j = 0; j < 8; j++) {
            int n = n0 + tx * 8 + j;
            if (n < N)
                C[(size_t)m * N + n] = acc[i][j] + bias[n];
        }
    }
}

// ---------------- column stats: sum & sumsq over rows ----------------
__global__ void colstats_kernel(const float* __restrict__ Z,
                                float* __restrict__ sum,
                                float* __restrict__ sumsq,
                                int M, int N)
{
    int j = blockIdx.x * 32 + threadIdx.x;
    int rows_per = M / gridDim.y;
    int r0 = blockIdx.y * rows_per;
    float s = 0.f, sq = 0.f;
    if (j < N) {
        for (int r = r0 + threadIdx.y; r < r0 + rows_per; r += 8) {
            float v = Z[(size_t)r * N + j];
            s += v; sq += v * v;
        }
    }
    __shared__ float sh[8][2][32];
    sh[threadIdx.y][0][threadIdx.x] = s;
    sh[threadIdx.y][1][threadIdx.x] = sq;
    __syncthreads();
    if (threadIdx.y == 0 && j < N) {
        float ts = 0.f, tq = 0.f;
        #pragma unroll
        for (int y = 0; y < 8; y++) { ts += sh[y][0][threadIdx.x]; tq += sh[y][1][threadIdx.x]; }
        atomicAdd(&sum[j], ts);
        atomicAdd(&sumsq[j], tq);
    }
}

// ---------------- BN1 fold: alpha1/beta1 ----------------
__global__ void prep1_kernel(const float* __restrict__ stats,
                             const float* __restrict__ g1,
                             const float* __restrict__ be1,
                             float* __restrict__ coef)
{
    int j = blockIdx.x * blockDim.x + threadIdx.x;
    if (j < NH) {
        float mean = stats[j] * (1.f / N_ROWS);
        float var  = stats[NH + j] * (1.f / N_ROWS) - mean * mean;
        float a = g1[j] * rsqrtf(var + EPS);
        coef[j]      = a;              // alpha1
        coef[NH + j] = be1[j] - a * mean; // beta1
    }
}

// ---------------- BN2 fold: a2[j] and scalar C ----------------
__global__ void prep2_kernel(const float* __restrict__ stats,
                             const float* __restrict__ g2,
                             const float* __restrict__ be2,
                             float* __restrict__ coef)
{
    int j = threadIdx.x;
    float c = 0.f;
    if (j < NH) {
        float mean = stats[2 * NH + j] * (1.f / N_ROWS);
        float var  = stats[3 * NH + j] * (1.f / N_ROWS) - mean * mean;
        float a = g2[j] * rsqrtf(var + EPS);
        coef[2 * NH + j] = a;           // a2
        c = be2[j] - a * mean;
    }
    __shared__ float sh[512];
    sh[j] = c;
    __syncthreads();
    for (int s = 256; s > 0; s >>= 1) {
        if (j < s) sh[j] += sh[j + s];
        __syncthreads();
    }
    if (j == 0) coef[3 * NH] = sh[0];   // C
}

// ---------------- final: out[n] += sum_j a2[j]*Z2[n,j] + C ----------------
__global__ void __launch_bounds__(256) rowdot_kernel(
    const float* __restrict__ Z2, const float* __restrict__ coef,
    float* __restrict__ out)
{
    __shared__ float a_s[NH];
    __shared__ float Cs;
    int t = threadIdx.x;
    for (int j = t; j < NH; j += 256) a_s[j] = coef[2 * NH + j];
    if (t == 0) Cs = coef[3 * NH];
    __syncthreads();

    int lane = t & 31, w = t >> 5;
    int row = blockIdx.x * 8 + w;
    float acc = 0.f;
    for (int j = lane; j < NH; j += 32)
        acc += a_s[j] * Z2[(size_t)row * NH + j];
    #pragma unroll
    for (int off = 16; off > 0; off >>= 1)
        acc += __shfl_down_sync(0xFFFFFFFF, acc, off);
    if (lane == 0)
        out[row] += acc + Cs;
}

// ---------------- launch ----------------
extern "C" void kernel_launch(void* const* d_in, const int* in_sizes, int n_in,
                              void* d_out, int out_size)
{
    const int*   xi   = (const int*)  d_in[0];
    const float* xv   = (const float*)d_in[1];
    const float* emb1 = (const float*)d_in[2];
    const float* emb2 = (const float*)d_in[3];
    const float* W1   = (const float*)d_in[4];
    const float* b1   = (const float*)d_in[5];
    const float* g1   = (const float*)d_in[6];
    const float* be1  = (const float*)d_in[7];
    const float* W2   = (const float*)d_in[8];
    const float* b2   = (const float*)d_in[9];
    const float* g2   = (const float*)d_in[10];
    const float* be2  = (const float*)d_in[11];
    const float* bias = (const float*)d_in[12];
    float* out = (float*)d_out;

    float *deep, *Z1, *Z2, *stats, *coef;
    cudaGetSymbolAddress((void**)&deep,  g_deep);
    cudaGetSymbolAddress((void**)&Z1,    g_Z1);
    cudaGetSymbolAddress((void**)&Z2,    g_Z2);
    cudaGetSymbolAddress((void**)&stats, g_stats);
    cudaGetSymbolAddress((void**)&coef,  g_coef);

    // 0. zero stats accumulators
    zero_kernel<<<(4 * NH + 255) / 256, 256>>>(stats);

    // 1. gather + e1 + fm2 + deep
    embed_kernel<<<N_ROWS, 640>>>(xi, xv, emb1, emb2, bias, deep, out);

    // 2. GEMM1: Z1 = deep @ W1 + b1
    dim3 g1grid((NH + 63) / 64, N_ROWS / 128);
    sgemm_kernel<false><<<g1grid, 128>>>(deep, W1, b1, Z1,
                                         N_ROWS, NH, ND, nullptr, nullptr);

    // 3. BN1 stats
    dim3 csgrid((NH + 31) / 32, 64);
    colstats_kernel<<<csgrid, dim3(32, 8)>>>(Z1, stats, stats + NH, N_ROWS, NH);
    prep1_kernel<<<2, 256>>>(stats, g1, be1, coef);

    // 4. GEMM2: Z2 = BN1(Z1) @ W2 + b2  (BN1 folded into A load)
    sgemm_kernel<true><<<g1grid, 128>>>(Z1, W2, b2, Z2,
                                        N_ROWS, NH, NH, coef, coef + NH);

    // 5. BN2 stats + fold
    colstats_kernel<<<csgrid, dim3(32, 8)>>>(Z2, stats + 2 * NH, stats + 3 * NH,
                                             N_ROWS, NH);
    prep2_kernel<<<1, 512>>>(stats, g2, be2, coef);

    // 6. final weighted row-sum
    rowdot_kernel<<<N_ROWS / 8, 256>>>(Z2, coef, out);
}

// round 3
// speedup vs baseline: 1.6728x; 1.6728x over previous
#include <cuda_runtime.h>
#include <cuda_bf16.h>
#include <cstdint>
#include <math.h>

#define N_ROWS 16384
#define NF     39
#define VP1    100001
#define NE     16
#define ND     624   // F*E
#define NH     400
#define EPS    1e-5f

#define KP1 640   // ND padded to multiple of 32
#define NC1 20    // KP1/32
#define KP2 448   // NH padded to multiple of 32
#define NC2 14    // KP2/32

// ---------------- scratch (static __device__, no allocations) ----------------
__device__ __align__(16) __nv_bfloat16 g_A1h[(size_t)N_ROWS * KP1];
__device__ __align__(16) __nv_bfloat16 g_A1l[(size_t)N_ROWS * KP1];
__device__ __align__(16) __nv_bfloat16 g_A2h[(size_t)N_ROWS * KP2];
__device__ __align__(16) __nv_bfloat16 g_A2l[(size_t)N_ROWS * KP2];
__device__ __align__(16) __nv_bfloat16 g_W1h[(size_t)NH * KP1];
__device__ __align__(16) __nv_bfloat16 g_W1l[(size_t)NH * KP1];
__device__ __align__(16) __nv_bfloat16 g_W2h[(size_t)NH * KP2];
__device__ __align__(16) __nv_bfloat16 g_W2l[(size_t)NH * KP2];
__device__ __align__(16) float g_Z1[(size_t)N_ROWS * NH];
__device__ __align__(16) float g_Z2[(size_t)N_ROWS * NH];
__device__ float g_stats[4 * NH];
__device__ float g_coef [3 * NH + 1];

// ---------------- helpers ----------------
__device__ __forceinline__ uint32_t smem_u32(const void* p) {
    uint32_t a;
    asm("{ .reg .u64 t; cvta.to.shared.u64 t, %1; cvt.u32.u64 %0, t; }"
        : "=r"(a) : "l"(p));
    return a;
}

__device__ __forceinline__ void cpa16(uint32_t dst, const void* src) {
    asm volatile("cp.async.cg.shared.global [%0], [%1], 16;"
                 :: "r"(dst), "l"(src));
}

#define CP_COMMIT() asm volatile("cp.async.commit_group;" ::: "memory")
#define CP_WAIT1()  asm volatile("cp.async.wait_group 1;" ::: "memory")
#define CP_WAIT0()  asm volatile("cp.async.wait_group 0;" ::: "memory")

#define LDSM_X4(r, addr) \
    asm volatile("ldmatrix.sync.aligned.m8n8.x4.shared.b16 {%0,%1,%2,%3}, [%4];" \
        : "=r"((r)[0]), "=r"((r)[1]), "=r"((r)[2]), "=r"((r)[3]) : "r"(addr))

#define MMA16816(d, a, b0, b1) \
    asm volatile("mma.sync.aligned.m16n8k16.row.col.f32.bf16.bf16.f32 " \
        "{%0,%1,%2,%3}, {%4,%5,%6,%7}, {%8,%9}, {%0,%1,%2,%3};" \
        : "+f"((d)[0]), "+f"((d)[1]), "+f"((d)[2]), "+f"((d)[3]) \
        : "r"((a)[0]), "r"((a)[1]), "r"((a)[2]), "r"((a)[3]), \
          "r"(b0), "r"(b1))

__device__ __forceinline__ void split_bf16(float x, __nv_bfloat16& h, __nv_bfloat16& l) {
    h = __float2bfloat16(x);
    l = __float2bfloat16(x - __bfloat162float(h));
}

// ---------------- zero stats ----------------
__global__ void zero_kernel(float* stats) {
    int i = blockIdx.x * blockDim.x + threadIdx.x;
    if (i < 4 * NH) stats[i] = 0.f;
}

// ---------------- embedding gather + e1 + FM2 + split deep ----------------
__global__ void __launch_bounds__(640) embed_kernel(
    const int* __restrict__ xi, const float* __restrict__ xv,
    const float* __restrict__ emb1, const float* __restrict__ emb2,
    const float* __restrict__ bias,
    __nv_bfloat16* __restrict__ Ah, __nv_bfloat16* __restrict__ Al,
    float* __restrict__ out)
{
    int n = blockIdx.x;
    int t = threadIdx.x;
    __shared__ int   idx_s[NF];
    __shared__ float xv_s[NF];
    __shared__ float vals[ND];
    __shared__ float e1s[NF];
    __shared__ float fm2s[NE];

    if (t < NF) {
        idx_s[t] = xi[n * NF + t];
        xv_s[t]  = xv[n * NF + t];
    }
    __syncthreads();

    if (t < KP1) {
        float v = 0.f;
        if (t < ND) {
            int f = t >> 4, e = t & 15;
            size_t off = ((size_t)f * VP1 + idx_s[f]) * NE + e;
            v = emb2[off] * xv_s[f];
            vals[t] = v;
        }
        __nv_bfloat16 h, l; split_bf16(v, h, l);
        Ah[(size_t)n * KP1 + t] = h;
        Al[(size_t)n * KP1 + t] = l;
    }
    if (t < NF) e1s[t] = emb1[(size_t)t * VP1 + idx_s[t]] * xv_s[t];
    __syncthreads();

    if (t < NE) {
        float s = 0.f, sq = 0.f;
        #pragma unroll
        for (int f = 0; f < NF; f++) {
            float v = vals[f * NE + t];
            s += v; sq += v * v;
        }
        fm2s[t] = 0.5f * (s * s - sq);
    }
    __syncthreads();

    if (t == 0) {
        float tot = bias[0];
        #pragma unroll
        for (int i = 0; i < NF; i++) tot += e1s[i];
        #pragma unroll
        for (int i = 0; i < NE; i++) tot += fm2s[i];
        out[n] = tot;
    }
}

// ---------------- W repack: transpose + split (Wt[n][k] = W[k][n]) ----------------
__global__ void repackW_kernel(const float* __restrict__ W,
                               __nv_bfloat16* __restrict__ Wh,
                               __nv_bfloat16* __restrict__ Wl,
                               int K, int Kpad)
{
    size_t idx = (size_t)blockIdx.x * blockDim.x + threadIdx.x;
    if (idx >= (size_t)NH * Kpad) return;
    int k = (int)(idx % Kpad);
    int n = (int)(idx / Kpad);
    float v = (k < K) ? W[(size_t)k * NH + n] : 0.f;
    __nv_bfloat16 h, l; split_bf16(v, h, l);
    Wh[idx] = h; Wl[idx] = l;
}

// ---------------- BN1 fold + split for GEMM2 A ----------------
__global__ void bn1split_kernel(const float* __restrict__ Z1,
                                const float* __restrict__ coef,
                                __nv_bfloat16* __restrict__ Ah,
                                __nv_bfloat16* __restrict__ Al)
{
    size_t idx = (size_t)blockIdx.x * blockDim.x + threadIdx.x;
    if (idx >= (size_t)N_ROWS * KP2) return;
    int k = (int)(idx % KP2);
    size_t m = idx / KP2;
    float x = 0.f;
    if (k < NH) x = coef[k] * Z1[m * NH + k] + coef[NH + k];
    __nv_bfloat16 h, l; split_bf16(x, h, l);
    Ah[idx] = h; Al[idx] = l;
}

// ---------------- HMMA GEMM: C = (Ah+Al) @ (Bh+Bl)^T + bias ----------------
// A: [M, Kpad] bf16 row-major (hi/lo). B: [NH, Kpad] bf16 row-major (hi/lo).
// BM=128, BN=80, BK=32. 256 threads = 8 warps, warp tile 16x80.
// SMEM rows padded to 40 bf16 (80B) for conflict-free ldmatrix.
// Per-buffer bf16 offsets: A_h 0 (128*40), A_l 5120, B_h 10240 (80*40), B_l 13440.
// Buffer size 16640 bf16 = 33280 B; double buffered.
__global__ void __launch_bounds__(256) hmma_gemm_kernel(
    const __nv_bfloat16* __restrict__ Ah, const __nv_bfloat16* __restrict__ Al,
    const __nv_bfloat16* __restrict__ Bh, const __nv_bfloat16* __restrict__ Bl,
    const float* __restrict__ bias, float* __restrict__ C,
    int Kpad, int nchunk)
{
    extern __shared__ __nv_bfloat16 smem[];
    const int BUF = 16640;                      // bf16 per buffer
    const uint32_t sbase = smem_u32(smem);

    int tid = threadIdx.x;
    int wid = tid >> 5, lane = tid & 31;
    int n0 = blockIdx.x * 80;
    int m0 = blockIdx.y * 128;

    float acc[10][4];
    #pragma unroll
    for (int i = 0; i < 10; i++)
        #pragma unroll
        for (int j = 0; j < 4; j++) acc[i][j] = 0.f;

    // ---- async tile loader ----
    auto load_chunk = [&](int buf, int kc) {
        uint32_t sb = sbase + (uint32_t)buf * BUF * 2;
        int k0 = kc * 32;
        // A: 128 rows x 32 cols, 16B granules: 512 per split, 2 per thread
        #pragma unroll
        for (int l = 0; l < 2; l++) {
            int i = tid + l * 256;
            int row = i >> 2, c = (i & 3) * 8;
            size_t go = (size_t)(m0 + row) * Kpad + k0 + c;
            uint32_t d = sb + (uint32_t)(row * 40 + c) * 2;
            cpa16(d, Ah + go);
            cpa16(d + 5120 * 2, Al + go);
        }
        // B: 80 rows x 32 cols: 320 granules per split
        for (int i = tid; i < 320; i += 256) {
            int row = i >> 2, c = (i & 3) * 8;
            size_t go = (size_t)(n0 + row) * Kpad + k0 + c;
            uint32_t d = sb + (uint32_t)(10240 + row * 40 + c) * 2;
            cpa16(d, Bh + go);
            cpa16(d + 3200 * 2, Bl + go);
        }
        CP_COMMIT();
    };

    load_chunk(0, 0);

    for (int kc = 0; kc < nchunk; kc++) {
        int b = kc & 1;
        if (kc + 1 < nchunk) {
            load_chunk(1 - b, kc + 1);
            CP_WAIT1();
        } else {
            CP_WAIT0();
        }
        __syncthreads();

        uint32_t sb = sbase + (uint32_t)b * BUF * 2;
        #pragma unroll
        for (int ks = 0; ks < 2; ks++) {
            int k0s = ks * 16;
            // A fragments (m16 x k16), hi and lo
            uint32_t ah[4], al[4];
            uint32_t aaddr = sb + (uint32_t)((wid * 16 + (lane & 15)) * 40
                                             + k0s + (lane >> 4) * 8) * 2;
            LDSM_X4(ah, aaddr);
            LDSM_X4(al, aaddr + 5120 * 2);
            // B groups: 5 x (n16 x k16)
            #pragma unroll
            for (int g = 0; g < 5; g++) {
                uint32_t bh[4], bl[4];
                int rowB = g * 16 + (lane & 7) + ((lane >> 3) & 1) * 8;
                uint32_t baddr = sb + (uint32_t)(10240 + rowB * 40
                                                 + k0s + (lane >> 4) * 8) * 2;
                LDSM_X4(bh, baddr);
                LDSM_X4(bl, baddr + 3200 * 2);
                // n-tile 2g (n rows g*16..+7), n-tile 2g+1 (g*16+8..+15)
                MMA16816(acc[2 * g],     ah, bh[0], bh[2]);
                MMA16816(acc[2 * g],     ah, bl[0], bl[2]);
                MMA16816(acc[2 * g],     al, bh[0], bh[2]);
                MMA16816(acc[2 * g + 1], ah, bh[1], bh[3]);
                MMA16816(acc[2 * g + 1], ah, bl[1], bl[3]);
                MMA16816(acc[2 * g + 1], al, bh[1], bh[3]);
            }
        }
        __syncthreads();
    }

    // ---- epilogue: C[m][n] = acc + bias[n] ----
    int r0 = m0 + wid * 16 + (lane >> 2);
    int cb = n0 + (lane & 3) * 2;
    #pragma unroll
    for (int nt = 0; nt < 10; nt++) {
        int n = cb + nt * 8;
        float2 v0 = make_float2(acc[nt][0] + bias[n], acc[nt][1] + bias[n + 1]);
        float2 v1 = make_float2(acc[nt][2] + bias[n], acc[nt][3] + bias[n + 1]);
        *reinterpret_cast<float2*>(C + (size_t)r0 * NH + n) = v0;
        *reinterpret_cast<float2*>(C + (size_t)(r0 + 8) * NH + n) = v1;
    }
}

// ---------------- column stats ----------------
__global__ void colstats_kernel(const float* __restrict__ Z,
                                float* __restrict__ sum,
                                float* __restrict__ sumsq,
                                int M, int N)
{
    int j = blockIdx.x * 32 + threadIdx.x;
    int rows_per = M / gridDim.y;
    int r0 = blockIdx.y * rows_per;
    float s = 0.f, sq = 0.f;
    if (j < N) {
        for (int r = r0 + threadIdx.y; r < r0 + rows_per; r += 8) {
            float v = Z[(size_t)r * N + j];
            s += v; sq += v * v;
        }
    }
    __shared__ float sh[8][2][32];
    sh[threadIdx.y][0][threadIdx.x] = s;
    sh[threadIdx.y][1][threadIdx.x] = sq;
    __syncthreads();
    if (threadIdx.y == 0 && j < N) {
        float ts = 0.f, tq = 0.f;
        #pragma unroll
        for (int y = 0; y < 8; y++) { ts += sh[y][0][threadIdx.x]; tq += sh[y][1][threadIdx.x]; }
        atomicAdd(&sum[j], ts);
        atomicAdd(&sumsq[j], tq);
    }
}

// ---------------- BN folds ----------------
__global__ void prep1_kernel(const float* __restrict__ stats,
                             const float* __restrict__ g1,
                             const float* __restrict__ be1,
                             float* __restrict__ coef)
{
    int j = blockIdx.x * blockDim.x + threadIdx.x;
    if (j < NH) {
        float mean = stats[j] * (1.f / N_ROWS);
        float var  = stats[NH + j] * (1.f / N_ROWS) - mean * mean;
        float a = g1[j] * rsqrtf(var + EPS);
        coef[j]      = a;
        coef[NH + j] = be1[j] - a * mean;
    }
}

__global__ void prep2_kernel(const float* __restrict__ stats,
                             const float* __restrict__ g2,
                             const float* __restrict__ be2,
                             float* __restrict__ coef)
{
    int j = threadIdx.x;
    float c = 0.f;
    if (j < NH) {
        float mean = stats[2 * NH + j] * (1.f / N_ROWS);
        float var  = stats[3 * NH + j] * (1.f / N_ROWS) - mean * mean;
        float a = g2[j] * rsqrtf(var + EPS);
        coef[2 * NH + j] = a;
        c = be2[j] - a * mean;
    }
    __shared__ float sh[512];
    sh[j] = c;
    __syncthreads();
    for (int s = 256; s > 0; s >>= 1) {
        if (j < s) sh[j] += sh[j + s];
        __syncthreads();
    }
    if (j == 0) coef[3 * NH] = sh[0];
}

// ---------------- final weighted row-sum ----------------
__global__ void __launch_bounds__(256) rowdot_kernel(
    const float* __restrict__ Z2, const float* __restrict__ coef,
    float* __restrict__ out)
{
    __shared__ float a_s[NH];
    __shared__ float Cs;
    int t = threadIdx.x;
    for (int j = t; j < NH; j += 256) a_s[j] = coef[2 * NH + j];
    if (t == 0) Cs = coef[3 * NH];
    __syncthreads();

    int lane = t & 31, w = t >> 5;
    int row = blockIdx.x * 8 + w;
    float acc = 0.f;
    for (int j = lane; j < NH; j += 32)
        acc += a_s[j] * Z2[(size_t)row * NH + j];
    #pragma unroll
    for (int off = 16; off > 0; off >>= 1)
        acc += __shfl_down_sync(0xFFFFFFFF, acc, off);
    if (lane == 0)
        out[row] += acc + Cs;
}

// ---------------- launch ----------------
extern "C" void kernel_launch(void* const* d_in, const int* in_sizes, int n_in,
                              void* d_out, int out_size)
{
    const int*   xi   = (const int*)  d_in[0];
    const float* xv   = (const float*)d_in[1];
    const float* emb1 = (const float*)d_in[2];
    const float* emb2 = (const float*)d_in[3];
    const float* W1   = (const float*)d_in[4];
    const float* b1   = (const float*)d_in[5];
    const float* g1   = (const float*)d_in[6];
    const float* be1  = (const float*)d_in[7];
    const float* W2   = (const float*)d_in[8];
    const float* b2   = (const float*)d_in[9];
    const float* g2   = (const float*)d_in[10];
    const float* be2  = (const float*)d_in[11];
    const float* bias = (const float*)d_in[12];
    float* out = (float*)d_out;

    __nv_bfloat16 *A1h, *A1l, *A2h, *A2l, *W1h, *W1l, *W2h, *W2l;
    float *Z1, *Z2, *stats, *coef;
    cudaGetSymbolAddress((void**)&A1h, g_A1h);
    cudaGetSymbolAddress((void**)&A1l, g_A1l);
    cudaGetSymbolAddress((void**)&A2h, g_A2h);
    cudaGetSymbolAddress((void**)&A2l, g_A2l);
    cudaGetSymbolAddress((void**)&W1h, g_W1h);
    cudaGetSymbolAddress((void**)&W1l, g_W1l);
    cudaGetSymbolAddress((void**)&W2h, g_W2h);
    cudaGetSymbolAddress((void**)&W2l, g_W2l);
    cudaGetSymbolAddress((void**)&Z1,  g_Z1);
    cudaGetSymbolAddress((void**)&Z2,  g_Z2);
    cudaGetSymbolAddress((void**)&stats, g_stats);
    cudaGetSymbolAddress((void**)&coef,  g_coef);

    const int SMEM_BYTES = 2 * 16640 * 2;   // 66560
    cudaFuncSetAttribute(hmma_gemm_kernel,
                         cudaFuncAttributeMaxDynamicSharedMemorySize, SMEM_BYTES);

    zero_kernel<<<(4 * NH + 255) / 256, 256>>>(stats);
    embed_kernel<<<N_ROWS, 640>>>(xi, xv, emb1, emb2, bias, A1h, A1l, out);

    repackW_kernel<<<((size_t)NH * KP1 + 255) / 256, 256>>>(W1, W1h, W1l, ND, KP1);
    repackW_kernel<<<((size_t)NH * KP2 + 255) / 256, 256>>>(W2, W2h, W2l, NH, KP2);

    dim3 ggrid(5, N_ROWS / 128);
    hmma_gemm_kernel<<<ggrid, 256, SMEM_BYTES>>>(A1h, A1l, W1h, W1l, b1, Z1, KP1, NC1);

    dim3 csgrid((NH + 31) / 32, 64);
    colstats_kernel<<<csgrid, dim3(32, 8)>>>(Z1, stats, stats + NH, N_ROWS, NH);
    prep1_kernel<<<2, 256>>>(stats, g1, be1, coef);

    bn1split_kernel<<<((size_t)N_ROWS * KP2 + 255) / 256, 256>>>(Z1, coef, A2h, A2l);
    hmma_gemm_kernel<<<ggrid, 256, SMEM_BYTES>>>(A2h, A2l, W2h, W2l, b2, Z2, KP2, NC2);

    colstats_kernel<<<csgrid, dim3(32, 8)>>>(Z2, stats + 2 * NH, stats + 3 * NH, N_ROWS, NH);
    prep2_kernel<<<1, 512>>>(stats, g2, be2, coef);

    rowdot_kernel<<<N_ROWS / 8, 256>>>(Z2, coef, out);
}

// round 4
// speedup vs baseline: 1.7028x; 1.0180x over previous
#include <cuda_runtime.h>
#include <cuda_bf16.h>
#include <cstdint>
#include <math.h>

#define N_ROWS 16384
#define NF     39
#define VP1    100001
#define NE     16
#define ND     624   // F*E
#define NH     400
#define EPS    1e-5f

#define KP1 640   // ND padded to multiple of 32
#define NC1 20    // KP1/32
#define KP2 448   // NH padded to multiple of 32
#define NC2 14    // KP2/32

// ---------------- scratch (static __device__, no allocations) ----------------
__device__ __align__(16) __nv_bfloat16 g_A1h[(size_t)N_ROWS * KP1];
__device__ __align__(16) __nv_bfloat16 g_A1l[(size_t)N_ROWS * KP1];
__device__ __align__(16) __nv_bfloat16 g_Z1h[(size_t)N_ROWS * KP2];
__device__ __align__(16) __nv_bfloat16 g_Z1l[(size_t)N_ROWS * KP2];
__device__ __align__(16) __nv_bfloat16 g_W1h[(size_t)NH * KP1];
__device__ __align__(16) __nv_bfloat16 g_W1l[(size_t)NH * KP1];
__device__ __align__(16) __nv_bfloat16 g_W2h[(size_t)NH * KP2];
__device__ __align__(16) __nv_bfloat16 g_W2l[(size_t)NH * KP2];
__device__ __align__(16) float g_Z2[(size_t)N_ROWS * NH];
__device__ float g_stats[4 * NH];
__device__ float g_coef [3 * NH + 1];  // a1[400], b1fold[400], a2[400], C
__device__ float g_c2   [NH];

// ---------------- helpers ----------------
__device__ __forceinline__ uint32_t smem_u32(const void* p) {
    uint32_t a;
    asm("{ .reg .u64 t; cvta.to.shared.u64 t, %1; cvt.u32.u64 %0, t; }"
        : "=r"(a) : "l"(p));
    return a;
}

__device__ __forceinline__ void cpa16(uint32_t dst, const void* src) {
    asm volatile("cp.async.cg.shared.global [%0], [%1], 16;"
                 :: "r"(dst), "l"(src));
}

#define CP_COMMIT() asm volatile("cp.async.commit_group;" ::: "memory")
#define CP_WAIT1()  asm volatile("cp.async.wait_group 1;" ::: "memory")

#define LDSM_X4(r, addr) \
    asm volatile("ldmatrix.sync.aligned.m8n8.x4.shared.b16 {%0,%1,%2,%3}, [%4];" \
        : "=r"((r)[0]), "=r"((r)[1]), "=r"((r)[2]), "=r"((r)[3]) : "r"(addr))

#define MMA16816(d, a, b0, b1) \
    asm volatile("mma.sync.aligned.m16n8k16.row.col.f32.bf16.bf16.f32 " \
        "{%0,%1,%2,%3}, {%4,%5,%6,%7}, {%8,%9}, {%0,%1,%2,%3};" \
        : "+f"((d)[0]), "+f"((d)[1]), "+f"((d)[2]), "+f"((d)[3]) \
        : "r"((a)[0]), "r"((a)[1]), "r"((a)[2]), "r"((a)[3]), \
          "r"(b0), "r"(b1))

__device__ __forceinline__ void split_bf16(float x, __nv_bfloat16& h, __nv_bfloat16& l) {
    h = __float2bfloat16(x);
    l = __float2bfloat16(x - __bfloat162float(h));
}

// ---------------- zero stats ----------------
__global__ void zero_kernel(float* stats) {
    int i = blockIdx.x * blockDim.x + threadIdx.x;
    if (i < 4 * NH) stats[i] = 0.f;
}

// ---------------- embedding gather + e1 + FM2 + split deep ----------------
__global__ void __launch_bounds__(640) embed_kernel(
    const int* __restrict__ xi, const float* __restrict__ xv,
    const float* __restrict__ emb1, const float* __restrict__ emb2,
    const float* __restrict__ bias,
    __nv_bfloat16* __restrict__ Ah, __nv_bfloat16* __restrict__ Al,
    float* __restrict__ out)
{
    int n = blockIdx.x;
    int t = threadIdx.x;
    __shared__ int   idx_s[NF];
    __shared__ float xv_s[NF];
    __shared__ float vals[ND];
    __shared__ float e1s[NF];
    __shared__ float fm2s[NE];

    if (t < NF) {
        idx_s[t] = xi[n * NF + t];
        xv_s[t]  = xv[n * NF + t];
    }
    __syncthreads();

    if (t < KP1) {
        float v = 0.f;
        if (t < ND) {
            int f = t >> 4, e = t & 15;
            size_t off = ((size_t)f * VP1 + idx_s[f]) * NE + e;
            v = emb2[off] * xv_s[f];
            vals[t] = v;
        }
        __nv_bfloat16 h, l; split_bf16(v, h, l);
        Ah[(size_t)n * KP1 + t] = h;
        Al[(size_t)n * KP1 + t] = l;
    }
    if (t < NF) e1s[t] = emb1[(size_t)t * VP1 + idx_s[t]] * xv_s[t];
    __syncthreads();

    if (t < NE) {
        float s = 0.f, sq = 0.f;
        #pragma unroll
        for (int f = 0; f < NF; f++) {
            float v = vals[f * NE + t];
            s += v; sq += v * v;
        }
        fm2s[t] = 0.5f * (s * s - sq);
    }
    __syncthreads();

    if (t == 0) {
        float tot = bias[0];
        #pragma unroll
        for (int i = 0; i < NF; i++) tot += e1s[i];
        #pragma unroll
        for (int i = 0; i < NE; i++) tot += fm2s[i];
        out[n] = tot;
    }
}

// ---------------- W1 repack: transpose + split ----------------
__global__ void repackW_kernel(const float* __restrict__ W,
                               __nv_bfloat16* __restrict__ Wh,
                               __nv_bfloat16* __restrict__ Wl,
                               int K, int Kpad)
{
    size_t idx = (size_t)blockIdx.x * blockDim.x + threadIdx.x;
    if (idx >= (size_t)NH * Kpad) return;
    int k = (int)(idx % Kpad);
    int n = (int)(idx / Kpad);
    float v = (k < K) ? W[(size_t)k * NH + n] : 0.f;
    __nv_bfloat16 h, l; split_bf16(v, h, l);
    Wh[idx] = h; Wl[idx] = l;
}

// ---------------- BN1 fold ----------------
__global__ void prep1_kernel(const float* __restrict__ stats,
                             const float* __restrict__ g1,
                             const float* __restrict__ be1,
                             float* __restrict__ coef)
{
    int j = blockIdx.x * blockDim.x + threadIdx.x;
    if (j < NH) {
        float mean = stats[j] * (1.f / N_ROWS);
        float var  = stats[NH + j] * (1.f / N_ROWS) - mean * mean;
        float a = g1[j] * rsqrtf(var + EPS);
        coef[j]      = a;                 // scale
        coef[NH + j] = be1[j] - a * mean; // shift
    }
}

// ---------------- W2 repack with BN1 scale folded in, plus c2 vector ----------
// W2t'[n][k] = a_k * W2[k][n];  c2[n] = sum_k shift_k * W2[k][n] + b2[n]
__global__ void __launch_bounds__(128) repackW2c_kernel(
    const float* __restrict__ W2, const float* __restrict__ b2,
    const float* __restrict__ coef,
    __nv_bfloat16* __restrict__ Wh, __nv_bfloat16* __restrict__ Wl,
    float* __restrict__ c2)
{
    int n = blockIdx.x;
    int t = threadIdx.x;
    float partial = 0.f;
    for (int k = t; k < KP2; k += 128) {
        float w = 0.f, a = 0.f, sh = 0.f;
        if (k < NH) {
            w  = W2[(size_t)k * NH + n];
            a  = coef[k];
            sh = coef[NH + k];
        }
        __nv_bfloat16 h, l; split_bf16(a * w, h, l);
        Wh[(size_t)n * KP2 + k] = h;
        Wl[(size_t)n * KP2 + k] = l;
        partial += sh * w;
    }
    __shared__ float red[128];
    red[t] = partial;
    __syncthreads();
    for (int s = 64; s > 0; s >>= 1) {
        if (t < s) red[t] += red[t + s];
        __syncthreads();
    }
    if (t == 0) c2[n] = red[0] + b2[n];
}

// ---------------- HMMA GEMM: C = (Ah+Al) @ (Bh+Bl)^T + bias ------------------
// BM=128, BN=80, BK=32; 256 threads = 8 warps; warp tile 16x80.
// 3-stage cp.async pipeline. SMEM rows padded to 40 bf16 (80B).
// Per-buffer bf16 offsets: A_h 0 (128*40), A_l 5120, B_h 10240 (80*40), B_l 13440.
// EPI = 0: write split bf16 (Zh/Zl, stride KP2; zero-pad cols [400,448) when
//          n0 == 320) + column stats.
// EPI = 1: write fp32 (Zf, stride NH) + column stats.
template<int EPI>
__global__ void __launch_bounds__(256) hmma_gemm_kernel(
    const __nv_bfloat16* __restrict__ Ah, const __nv_bfloat16* __restrict__ Al,
    const __nv_bfloat16* __restrict__ Bh, const __nv_bfloat16* __restrict__ Bl,
    const float* __restrict__ bias,
    __nv_bfloat16* __restrict__ Zh, __nv_bfloat16* __restrict__ Zl,
    float* __restrict__ Zf,
    float* __restrict__ gsum, float* __restrict__ gsq,
    int Kpad, int nchunk)
{
    extern __shared__ __nv_bfloat16 smem[];
    const int BUF = 16640;                      // bf16 per buffer
    const uint32_t sbase = smem_u32(smem);

    int tid = threadIdx.x;
    int wid = tid >> 5, lane = tid & 31;
    int n0 = blockIdx.x * 80;
    int m0 = blockIdx.y * 128;

    float acc[10][4];
    #pragma unroll
    for (int i = 0; i < 10; i++)
        #pragma unroll
        for (int j = 0; j < 4; j++) acc[i][j] = 0.f;

    auto load_chunk = [&](int buf, int kc) {
        uint32_t sb = sbase + (uint32_t)buf * BUF * 2;
        int k0 = kc * 32;
        #pragma unroll
        for (int l = 0; l < 2; l++) {
            int i = tid + l * 256;
            int row = i >> 2, c = (i & 3) * 8;
            size_t go = (size_t)(m0 + row) * Kpad + k0 + c;
            uint32_t d = sb + (uint32_t)(row * 40 + c) * 2;
            cpa16(d, Ah + go);
            cpa16(d + 5120 * 2, Al + go);
        }
        for (int i = tid; i < 320; i += 256) {
            int row = i >> 2, c = (i & 3) * 8;
            size_t go = (size_t)(n0 + row) * Kpad + k0 + c;
            uint32_t d = sb + (uint32_t)(10240 + row * 40 + c) * 2;
            cpa16(d, Bh + go);
            cpa16(d + 3200 * 2, Bl + go);
        }
    };

    load_chunk(0, 0); CP_COMMIT();
    load_chunk(1, 1); CP_COMMIT();

    for (int kc = 0; kc < nchunk; kc++) {
        int b = kc % 3;
        CP_WAIT1();
        __syncthreads();
        if (kc + 2 < nchunk) load_chunk((kc + 2) % 3, kc + 2);
        CP_COMMIT();

        uint32_t sb = sbase + (uint32_t)b * BUF * 2;
        #pragma unroll
        for (int ks = 0; ks < 2; ks++) {
            int k0s = ks * 16;
            uint32_t ah[4], al[4];
            uint32_t aaddr = sb + (uint32_t)((wid * 16 + (lane & 15)) * 40
                                             + k0s + (lane >> 4) * 8) * 2;
            LDSM_X4(ah, aaddr);
            LDSM_X4(al, aaddr + 5120 * 2);
            #pragma unroll
            for (int g = 0; g < 5; g++) {
                uint32_t bh[4], bl[4];
                int rowB = g * 16 + (lane & 7) + ((lane >> 3) & 1) * 8;
                uint32_t baddr = sb + (uint32_t)(10240 + rowB * 40
                                                 + k0s + (lane >> 4) * 8) * 2;
                LDSM_X4(bh, baddr);
                LDSM_X4(bl, baddr + 3200 * 2);
                MMA16816(acc[2 * g],     ah, bh[0], bh[2]);
                MMA16816(acc[2 * g],     ah, bl[0], bl[2]);
                MMA16816(acc[2 * g],     al, bh[0], bh[2]);
                MMA16816(acc[2 * g + 1], ah, bh[1], bh[3]);
                MMA16816(acc[2 * g + 1], ah, bl[1], bl[3]);
                MMA16816(acc[2 * g + 1], al, bh[1], bh[3]);
            }
        }
    }

    // ---- epilogue ----
    __syncthreads();   // all cp.async groups drained (only empties pending)
    float* ssum = reinterpret_cast<float*>(smem);       // 80
    float* ssq  = ssum + 80;                            // 80
    for (int i = tid; i < 160; i += 256) ssum[i] = 0.f;
    __syncthreads();

    int r0 = m0 + wid * 16 + (lane >> 2);
    int cb = n0 + (lane & 3) * 2;
    #pragma unroll
    for (int nt = 0; nt < 10; nt++) {
        int n = cb + nt * 8;
        float bz0 = bias[n], bz1 = bias[n + 1];
        float v00 = acc[nt][0] + bz0, v01 = acc[nt][1] + bz1;
        float v10 = acc[nt][2] + bz0, v11 = acc[nt][3] + bz1;

        if (EPI == 0) {
            __nv_bfloat162 h0, l0, h1, l1;
            split_bf16(v00, h0.x, l0.x); split_bf16(v01, h0.y, l0.y);
            split_bf16(v10, h1.x, l1.x); split_bf16(v11, h1.y, l1.y);
            *reinterpret_cast<__nv_bfloat162*>(Zh + (size_t)r0 * KP2 + n) = h0;
            *reinterpret_cast<__nv_bfloat162*>(Zl + (size_t)r0 * KP2 + n) = l0;
            *reinterpret_cast<__nv_bfloat162*>(Zh + (size_t)(r0 + 8) * KP2 + n) = h1;
            *reinterpret_cast<__nv_bfloat162*>(Zl + (size_t)(r0 + 8) * KP2 + n) = l1;
        } else {
            *reinterpret_cast<float2*>(Zf + (size_t)r0 * NH + n) =
                make_float2(v00, v01);
            *reinterpret_cast<float2*>(Zf + (size_t)(r0 + 8) * NH + n) =
                make_float2(v10, v11);
        }

        float s0 = v00 + v10, q0 = v00 * v00 + v10 * v10;
        float s1 = v01 + v11, q1 = v01 * v01 + v11 * v11;
        #pragma unroll
        for (int off = 16; off >= 4; off >>= 1) {
            s0 += __shfl_down_sync(0xFFFFFFFF, s0, off);
            q0 += __shfl_down_sync(0xFFFFFFFF, q0, off);
            s1 += __shfl_down_sync(0xFFFFFFFF, s1, off);
            q1 += __shfl_down_sync(0xFFFFFFFF, q1, off);
        }
        if (lane < 4) {
            int lc = lane * 2 + nt * 8;
            atomicAdd(&ssum[lc],     s0);
            atomicAdd(&ssum[lc + 1], s1);
            atomicAdd(&ssq[lc],      q0);
            atomicAdd(&ssq[lc + 1],  q1);
        }
    }

    // zero-pad columns [400, 448) of the split output
    if (EPI == 0 && n0 == 320) {
        for (int i = tid; i < 1536; i += 256) {
            int row = i / 12, q = i % 12;
            size_t off = (size_t)(m0 + row) * KP2 + 400 + q * 4;
            *reinterpret_cast<uint2*>(Zh + off) = make_uint2(0u, 0u);
            *reinterpret_cast<uint2*>(Zl + off) = make_uint2(0u, 0u);
        }
    }

    __syncthreads();
    for (int i = tid; i < 80; i += 256) {
        atomicAdd(&gsum[n0 + i], ssum[i]);
        atomicAdd(&gsq[n0 + i],  ssq[i]);
    }
}

// ---------------- BN2 fold ----------------
__global__ void prep2_kernel(const float* __restrict__ stats,
                             const float* __restrict__ g2,
                             const float* __restrict__ be2,
                             float* __restrict__ coef)
{
    int j = threadIdx.x;
    float c = 0.f;
    if (j < NH) {
        float mean = stats[2 * NH + j] * (1.f / N_ROWS);
        float var  = stats[3 * NH + j] * (1.f / N_ROWS) - mean * mean;
        float a = g2[j] * rsqrtf(var + EPS);
        coef[2 * NH + j] = a;
        c = be2[j] - a * mean;
    }
    __shared__ float sh[512];
    sh[j] = c;
    __syncthreads();
    for (int s = 256; s > 0; s >>= 1) {
        if (j < s) sh[j] += sh[j + s];
        __syncthreads();
    }
    if (j == 0) coef[3 * NH] = sh[0];
}

// ---------------- final weighted row-sum ----------------
__global__ void __launch_bounds__(256) rowdot_kernel(
    const float* __restrict__ Z2, const float* __restrict__ coef,
    float* __restrict__ out)
{
    __shared__ float a_s[NH];
    __shared__ float Cs;
    int t = threadIdx.x;
    for (int j = t; j < NH; j += 256) a_s[j] = coef[2 * NH + j];
    if (t == 0) Cs = coef[3 * NH];
    __syncthreads();

    int lane = t & 31, w = t >> 5;
    int row = blockIdx.x * 8 + w;
    float acc = 0.f;
    for (int j = lane; j < NH; j += 32)
        acc += a_s[j] * Z2[(size_t)row * NH + j];
    #pragma unroll
    for (int off = 16; off > 0; off >>= 1)
        acc += __shfl_down_sync(0xFFFFFFFF, acc, off);
    if (lane == 0)
        out[row] += acc + Cs;
}

// ---------------- launch ----------------
extern "C" void kernel_launch(void* const* d_in, const int* in_sizes, int n_in,
                              void* d_out, int out_size)
{
    const int*   xi   = (const int*)  d_in[0];
    const float* xv   = (const float*)d_in[1];
    const float* emb1 = (const float*)d_in[2];
    const float* emb2 = (const float*)d_in[3];
    const float* W1   = (const float*)d_in[4];
    const float* b1   = (const float*)d_in[5];
    const float* g1   = (const float*)d_in[6];
    const float* be1  = (const float*)d_in[7];
    const float* W2   = (const float*)d_in[8];
    const float* b2   = (const float*)d_in[9];
    const float* g2   = (const float*)d_in[10];
    const float* be2  = (const float*)d_in[11];
    const float* bias = (const float*)d_in[12];
    float* out = (float*)d_out;

    __nv_bfloat16 *A1h, *A1l, *Z1h, *Z1l, *W1h, *W1l, *W2h, *W2l;
    float *Z2, *stats, *coef, *c2;
    cudaGetSymbolAddress((void**)&A1h, g_A1h);
    cudaGetSymbolAddress((void**)&A1l, g_A1l);
    cudaGetSymbolAddress((void**)&Z1h, g_Z1h);
    cudaGetSymbolAddress((void**)&Z1l, g_Z1l);
    cudaGetSymbolAddress((void**)&W1h, g_W1h);
    cudaGetSymbolAddress((void**)&W1l, g_W1l);
    cudaGetSymbolAddress((void**)&W2h, g_W2h);
    cudaGetSymbolAddress((void**)&W2l, g_W2l);
    cudaGetSymbolAddress((void**)&Z2,  g_Z2);
    cudaGetSymbolAddress((void**)&stats, g_stats);
    cudaGetSymbolAddress((void**)&coef,  g_coef);
    cudaGetSymbolAddress((void**)&c2,    g_c2);

    const int SMEM_BYTES = 3 * 16640 * 2;   // 99840
    cudaFuncSetAttribute(hmma_gemm_kernel<0>,
                         cudaFuncAttributeMaxDynamicSharedMemorySize, SMEM_BYTES);
    cudaFuncSetAttribute(hmma_gemm_kernel<1>,
                         cudaFuncAttributeMaxDynamicSharedMemorySize, SMEM_BYTES);

    zero_kernel<<<(4 * NH + 255) / 256, 256>>>(stats);
    embed_kernel<<<N_ROWS, 640>>>(xi, xv, emb1, emb2, bias, A1h, A1l, out);
    repackW_kernel<<<((size_t)NH * KP1 + 255) / 256, 256>>>(W1, W1h, W1l, ND, KP1);

    dim3 ggrid(5, N_ROWS / 128);
    // GEMM1: epilogue writes split Z1 + BN1 stats
    hmma_gemm_kernel<0><<<ggrid, 256, SMEM_BYTES>>>(
        A1h, A1l, W1h, W1l, b1, Z1h, Z1l, nullptr,
        stats, stats + NH, KP1, NC1);

    prep1_kernel<<<2, 256>>>(stats, g1, be1, coef);
    repackW2c_kernel<<<NH, 128>>>(W2, b2, coef, W2h, W2l, c2);

    // GEMM2: Z2 = Z1 @ (diag(a1) W2) + c2, epilogue writes fp32 Z2 + BN2 stats
    hmma_gemm_kernel<1><<<ggrid, 256, SMEM_BYTES>>>(
        Z1h, Z1l, W2h, W2l, c2, nullptr, nullptr, Z2,
        stats + 2 * NH, stats + 3 * NH, KP2, NC2);

    prep2_kernel<<<1, 512>>>(stats, g2, be2, coef);
    rowdot_kernel<<<N_ROWS / 8, 256>>>(Z2, coef, out);
}

// round 5
// speedup vs baseline: 1.7379x; 1.0206x over previous
#include <cuda_runtime.h>
#include <cuda_bf16.h>
#include <cstdint>
#include <math.h>

#define N_ROWS 16384
#define NF     39
#define VP1    100001
#define NE     16
#define ND     624   // F*E
#define NH     400
#define EPS    1e-5f

#define KP1 640   // ND padded to multiple of 32
#define NC1 20    // KP1/32
#define KP2 448   // NH padded to multiple of 32
#define NC2 14    // KP2/32

// ---------------- scratch (static __device__, no allocations) ----------------
__device__ __align__(16) __nv_bfloat16 g_A1h[(size_t)N_ROWS * KP1];
__device__ __align__(16) __nv_bfloat16 g_A1l[(size_t)N_ROWS * KP1];
__device__ __align__(16) __nv_bfloat16 g_Z1h[(size_t)N_ROWS * KP2];
__device__ __align__(16) __nv_bfloat16 g_Z1l[(size_t)N_ROWS * KP2];
__device__ __align__(16) __nv_bfloat16 g_W1h[(size_t)NH * KP1];
__device__ __align__(16) __nv_bfloat16 g_W1l[(size_t)NH * KP1];
__device__ __align__(16) __nv_bfloat16 g_W2h[(size_t)NH * KP2];
__device__ __align__(16) __nv_bfloat16 g_W2l[(size_t)NH * KP2];
__device__ __align__(16) float g_Z2[(size_t)N_ROWS * NH];
__device__ float g_stats[4 * NH];
__device__ float g_coef [3 * NH + 1];  // a1[400], b1fold[400], a2[400], C
__device__ float g_c2   [NH];

// ---------------- helpers ----------------
__device__ __forceinline__ uint32_t smem_u32(const void* p) {
    uint32_t a;
    asm("{ .reg .u64 t; cvta.to.shared.u64 t, %1; cvt.u32.u64 %0, t; }"
        : "=r"(a) : "l"(p));
    return a;
}

__device__ __forceinline__ void cpa16(uint32_t dst, const void* src) {
    asm volatile("cp.async.cg.shared.global [%0], [%1], 16;"
                 :: "r"(dst), "l"(src));
}

#define CP_COMMIT() asm volatile("cp.async.commit_group;" ::: "memory")
#define CP_WAIT1()  asm volatile("cp.async.wait_group 1;" ::: "memory")

#define LDSM_X4(r, addr) \
    asm volatile("ldmatrix.sync.aligned.m8n8.x4.shared.b16 {%0,%1,%2,%3}, [%4];" \
        : "=r"((r)[0]), "=r"((r)[1]), "=r"((r)[2]), "=r"((r)[3]) : "r"(addr))

#define MMA16816(d, a, b0, b1) \
    asm volatile("mma.sync.aligned.m16n8k16.row.col.f32.bf16.bf16.f32 " \
        "{%0,%1,%2,%3}, {%4,%5,%6,%7}, {%8,%9}, {%0,%1,%2,%3};" \
        : "+f"((d)[0]), "+f"((d)[1]), "+f"((d)[2]), "+f"((d)[3]) \
        : "r"((a)[0]), "r"((a)[1]), "r"((a)[2]), "r"((a)[3]), \
          "r"(b0), "r"(b1))

__device__ __forceinline__ void split_bf16(float x, __nv_bfloat16& h, __nv_bfloat16& l) {
    h = __float2bfloat16(x);
    l = __float2bfloat16(x - __bfloat162float(h));
}

// ---------------- zero stats ----------------
__global__ void zero_kernel(float* stats) {
    int i = blockIdx.x * blockDim.x + threadIdx.x;
    if (i < 4 * NH) stats[i] = 0.f;
}

// ---------------- embedding gather + e1 + FM2 + split deep ----------------
__global__ void __launch_bounds__(640) embed_kernel(
    const int* __restrict__ xi, const float* __restrict__ xv,
    const float* __restrict__ emb1, const float* __restrict__ emb2,
    const float* __restrict__ bias,
    __nv_bfloat16* __restrict__ Ah, __nv_bfloat16* __restrict__ Al,
    float* __restrict__ out)
{
    int n = blockIdx.x;
    int t = threadIdx.x;
    __shared__ int   idx_s[NF];
    __shared__ float xv_s[NF];
    __shared__ float vals[ND];
    __shared__ float e1s[NF];
    __shared__ float fm2s[NE];

    if (t < NF) {
        idx_s[t] = xi[n * NF + t];
        xv_s[t]  = xv[n * NF + t];
    }
    __syncthreads();

    if (t < KP1) {
        float v = 0.f;
        if (t < ND) {
            int f = t >> 4, e = t & 15;
            size_t off = ((size_t)f * VP1 + idx_s[f]) * NE + e;
            v = emb2[off] * xv_s[f];
            vals[t] = v;
        }
        __nv_bfloat16 h, l; split_bf16(v, h, l);
        Ah[(size_t)n * KP1 + t] = h;
        Al[(size_t)n * KP1 + t] = l;
    }
    if (t < NF) e1s[t] = emb1[(size_t)t * VP1 + idx_s[t]] * xv_s[t];
    __syncthreads();

    if (t < NE) {
        float s = 0.f, sq = 0.f;
        #pragma unroll
        for (int f = 0; f < NF; f++) {
            float v = vals[f * NE + t];
            s += v; sq += v * v;
        }
        fm2s[t] = 0.5f * (s * s - sq);
    }
    __syncthreads();

    if (t == 0) {
        float tot = bias[0];
        #pragma unroll
        for (int i = 0; i < NF; i++) tot += e1s[i];
        #pragma unroll
        for (int i = 0; i < NE; i++) tot += fm2s[i];
        out[n] = tot;
    }
}

// ---------------- W1 repack: transpose + split ----------------
__global__ void repackW_kernel(const float* __restrict__ W,
                               __nv_bfloat16* __restrict__ Wh,
                               __nv_bfloat16* __restrict__ Wl,
                               int K, int Kpad)
{
    size_t idx = (size_t)blockIdx.x * blockDim.x + threadIdx.x;
    if (idx >= (size_t)NH * Kpad) return;
    int k = (int)(idx % Kpad);
    int n = (int)(idx / Kpad);
    float v = (k < K) ? W[(size_t)k * NH + n] : 0.f;
    __nv_bfloat16 h, l; split_bf16(v, h, l);
    Wh[idx] = h; Wl[idx] = l;
}

// ---------------- BN1 fold ----------------
__global__ void prep1_kernel(const float* __restrict__ stats,
                             const float* __restrict__ g1,
                             const float* __restrict__ be1,
                             float* __restrict__ coef)
{
    int j = blockIdx.x * blockDim.x + threadIdx.x;
    if (j < NH) {
        float mean = stats[j] * (1.f / N_ROWS);
        float var  = stats[NH + j] * (1.f / N_ROWS) - mean * mean;
        float a = g1[j] * rsqrtf(var + EPS);
        coef[j]      = a;                 // scale
        coef[NH + j] = be1[j] - a * mean; // shift
    }
}

// ---------------- W2 repack with BN1 scale folded in, plus c2 vector ----------
__global__ void __launch_bounds__(128) repackW2c_kernel(
    const float* __restrict__ W2, const float* __restrict__ b2,
    const float* __restrict__ coef,
    __nv_bfloat16* __restrict__ Wh, __nv_bfloat16* __restrict__ Wl,
    float* __restrict__ c2)
{
    int n = blockIdx.x;
    int t = threadIdx.x;
    float partial = 0.f;
    for (int k = t; k < KP2; k += 128) {
        float w = 0.f, a = 0.f, sh = 0.f;
        if (k < NH) {
            w  = W2[(size_t)k * NH + n];
            a  = coef[k];
            sh = coef[NH + k];
        }
        __nv_bfloat16 h, l; split_bf16(a * w, h, l);
        Wh[(size_t)n * KP2 + k] = h;
        Wl[(size_t)n * KP2 + k] = l;
        partial += sh * w;
    }
    __shared__ float red[128];
    red[t] = partial;
    __syncthreads();
    for (int s = 64; s > 0; s >>= 1) {
        if (t < s) red[t] += red[t + s];
        __syncthreads();
    }
    if (t == 0) c2[n] = red[0] + b2[n];
}

// ---------------- HMMA GEMM: C = (Ah+Al) @ (Bh+Bl)^T + bias ------------------
// BM=128, BN=80, BK=32; 256 threads = 8 warps; warp tile 16x80.
// 3-stage cp.async pipeline. Pass-major MMA ordering: per k16 step,
//   hh-pass over 10 acc tiles, lh-pass over 10, then hl-pass over 10
// so each accumulator is reused only every 10 MMAs (no RAW stalls).
template<int EPI>
__global__ void __launch_bounds__(256) hmma_gemm_kernel(
    const __nv_bfloat16* __restrict__ Ah, const __nv_bfloat16* __restrict__ Al,
    const __nv_bfloat16* __restrict__ Bh, const __nv_bfloat16* __restrict__ Bl,
    const float* __restrict__ bias,
    __nv_bfloat16* __restrict__ Zh, __nv_bfloat16* __restrict__ Zl,
    float* __restrict__ Zf,
    float* __restrict__ gsum, float* __restrict__ gsq,
    int Kpad, int nchunk)
{
    extern __shared__ __nv_bfloat16 smem[];
    const int BUF = 16640;                      // bf16 per buffer
    const uint32_t sbase = smem_u32(smem);

    int tid = threadIdx.x;
    int wid = tid >> 5, lane = tid & 31;
    int n0 = blockIdx.x * 80;
    int m0 = blockIdx.y * 128;

    float acc[10][4];
    #pragma unroll
    for (int i = 0; i < 10; i++)
        #pragma unroll
        for (int j = 0; j < 4; j++) acc[i][j] = 0.f;

    auto load_chunk = [&](int buf, int kc) {
        uint32_t sb = sbase + (uint32_t)buf * BUF * 2;
        int k0 = kc * 32;
        #pragma unroll
        for (int l = 0; l < 2; l++) {
            int i = tid + l * 256;
            int row = i >> 2, c = (i & 3) * 8;
            size_t go = (size_t)(m0 + row) * Kpad + k0 + c;
            uint32_t d = sb + (uint32_t)(row * 40 + c) * 2;
            cpa16(d, Ah + go);
            cpa16(d + 5120 * 2, Al + go);
        }
        for (int i = tid; i < 320; i += 256) {
            int row = i >> 2, c = (i & 3) * 8;
            size_t go = (size_t)(n0 + row) * Kpad + k0 + c;
            uint32_t d = sb + (uint32_t)(10240 + row * 40 + c) * 2;
            cpa16(d, Bh + go);
            cpa16(d + 3200 * 2, Bl + go);
        }
    };

    load_chunk(0, 0); CP_COMMIT();
    load_chunk(1, 1); CP_COMMIT();

    for (int kc = 0; kc < nchunk; kc++) {
        int b = kc % 3;
        CP_WAIT1();
        __syncthreads();
        if (kc + 2 < nchunk) load_chunk((kc + 2) % 3, kc + 2);
        CP_COMMIT();

        uint32_t sb = sbase + (uint32_t)b * BUF * 2;
        #pragma unroll
        for (int ks = 0; ks < 2; ks++) {
            int k0s = ks * 16;
            // A fragments hi & lo
            uint32_t ah[4], al[4];
            uint32_t aaddr = sb + (uint32_t)((wid * 16 + (lane & 15)) * 40
                                             + k0s + (lane >> 4) * 8) * 2;
            LDSM_X4(ah, aaddr);
            LDSM_X4(al, aaddr + 5120 * 2);

            int rowB = (lane & 7) + ((lane >> 3) & 1) * 8;
            uint32_t bbase = sb + (uint32_t)(10240 + rowB * 40
                                             + k0s + (lane >> 4) * 8) * 2;
            // ---- B-hi fragments for all 5 groups ----
            uint32_t bh[5][4];
            #pragma unroll
            for (int g = 0; g < 5; g++)
                LDSM_X4(bh[g], bbase + (uint32_t)(g * 16 * 40) * 2);
            // pass 1: Ah x Bh
            #pragma unroll
            for (int g = 0; g < 5; g++) {
                MMA16816(acc[2 * g],     ah, bh[g][0], bh[g][2]);
                MMA16816(acc[2 * g + 1], ah, bh[g][1], bh[g][3]);
            }
            // pass 2: Al x Bh
            #pragma unroll
            for (int g = 0; g < 5; g++) {
                MMA16816(acc[2 * g],     al, bh[g][0], bh[g][2]);
                MMA16816(acc[2 * g + 1], al, bh[g][1], bh[g][3]);
            }
            // ---- B-lo fragments ----
            uint32_t bl[5][4];
            #pragma unroll
            for (int g = 0; g < 5; g++)
                LDSM_X4(bl[g], bbase + (uint32_t)(3200 + g * 16 * 40) * 2);
            // pass 3: Ah x Bl
            #pragma unroll
            for (int g = 0; g < 5; g++) {
                MMA16816(acc[2 * g],     ah, bl[g][0], bl[g][2]);
                MMA16816(acc[2 * g + 1], ah, bl[g][1], bl[g][3]);
            }
        }
    }

    // ---- epilogue ----
    __syncthreads();
    float* ssum = reinterpret_cast<float*>(smem);       // 80
    float* ssq  = ssum + 80;                            // 80
    for (int i = tid; i < 160; i += 256) ssum[i] = 0.f;
    __syncthreads();

    int r0 = m0 + wid * 16 + (lane >> 2);
    int cb = n0 + (lane & 3) * 2;
    #pragma unroll
    for (int nt = 0; nt < 10; nt++) {
        int n = cb + nt * 8;
        float bz0 = bias[n], bz1 = bias[n + 1];
        float v00 = acc[nt][0] + bz0, v01 = acc[nt][1] + bz1;
        float v10 = acc[nt][2] + bz0, v11 = acc[nt][3] + bz1;

        if (EPI == 0) {
            __nv_bfloat162 h0, l0, h1, l1;
            split_bf16(v00, h0.x, l0.x); split_bf16(v01, h0.y, l0.y);
            split_bf16(v10, h1.x, l1.x); split_bf16(v11, h1.y, l1.y);
            *reinterpret_cast<__nv_bfloat162*>(Zh + (size_t)r0 * KP2 + n) = h0;
            *reinterpret_cast<__nv_bfloat162*>(Zl + (size_t)r0 * KP2 + n) = l0;
            *reinterpret_cast<__nv_bfloat162*>(Zh + (size_t)(r0 + 8) * KP2 + n) = h1;
            *reinterpret_cast<__nv_bfloat162*>(Zl + (size_t)(r0 + 8) * KP2 + n) = l1;
        } else {
            *reinterpret_cast<float2*>(Zf + (size_t)r0 * NH + n) =
                make_float2(v00, v01);
            *reinterpret_cast<float2*>(Zf + (size_t)(r0 + 8) * NH + n) =
                make_float2(v10, v11);
        }

        float s0 = v00 + v10, q0 = v00 * v00 + v10 * v10;
        float s1 = v01 + v11, q1 = v01 * v01 + v11 * v11;
        #pragma unroll
        for (int off = 16; off >= 4; off >>= 1) {
            s0 += __shfl_down_sync(0xFFFFFFFF, s0, off);
            q0 += __shfl_down_sync(0xFFFFFFFF, q0, off);
            s1 += __shfl_down_sync(0xFFFFFFFF, s1, off);
            q1 += __shfl_down_sync(0xFFFFFFFF, q1, off);
        }
        if (lane < 4) {
            int lc = lane * 2 + nt * 8;
            atomicAdd(&ssum[lc],     s0);
            atomicAdd(&ssum[lc + 1], s1);
            atomicAdd(&ssq[lc],      q0);
            atomicAdd(&ssq[lc + 1],  q1);
        }
    }

    if (EPI == 0 && n0 == 320) {
        for (int i = tid; i < 1536; i += 256) {
            int row = i / 12, q = i % 12;
            size_t off = (size_t)(m0 + row) * KP2 + 400 + q * 4;
            *reinterpret_cast<uint2*>(Zh + off) = make_uint2(0u, 0u);
            *reinterpret_cast<uint2*>(Zl + off) = make_uint2(0u, 0u);
        }
    }

    __syncthreads();
    for (int i = tid; i < 80; i += 256) {
        atomicAdd(&gsum[n0 + i], ssum[i]);
        atomicAdd(&gsq[n0 + i],  ssq[i]);
    }
}

// ---------------- BN2 fold ----------------
__global__ void prep2_kernel(const float* __restrict__ stats,
                             const float* __restrict__ g2,
                             const float* __restrict__ be2,
                             float* __restrict__ coef)
{
    int j = threadIdx.x;
    float c = 0.f;
    if (j < NH) {
        float mean = stats[2 * NH + j] * (1.f / N_ROWS);
        float var  = stats[3 * NH + j] * (1.f / N_ROWS) - mean * mean;
        float a = g2[j] * rsqrtf(var + EPS);
        coef[2 * NH + j] = a;
        c = be2[j] - a * mean;
    }
    __shared__ float sh[512];
    sh[j] = c;
    __syncthreads();
    for (int s = 256; s > 0; s >>= 1) {
        if (j < s) sh[j] += sh[j + s];
        __syncthreads();
    }
    if (j == 0) coef[3 * NH] = sh[0];
}

// ---------------- final weighted row-sum ----------------
__global__ void __launch_bounds__(256) rowdot_kernel(
    const float* __restrict__ Z2, const float* __restrict__ coef,
    float* __restrict__ out)
{
    __shared__ float a_s[NH];
    __shared__ float Cs;
    int t = threadIdx.x;
    for (int j = t; j < NH; j += 256) a_s[j] = coef[2 * NH + j];
    if (t == 0) Cs = coef[3 * NH];
    __syncthreads();

    int lane = t & 31, w = t >> 5;
    int row = blockIdx.x * 8 + w;
    float acc = 0.f;
    for (int j = lane; j < NH; j += 32)
        acc += a_s[j] * Z2[(size_t)row * NH + j];
    #pragma unroll
    for (int off = 16; off > 0; off >>= 1)
        acc += __shfl_down_sync(0xFFFFFFFF, acc, off);
    if (lane == 0)
        out[row] += acc + Cs;
}

// ---------------- launch ----------------
extern "C" void kernel_launch(void* const* d_in, const int* in_sizes, int n_in,
                              void* d_out, int out_size)
{
    const int*   xi   = (const int*)  d_in[0];
    const float* xv   = (const float*)d_in[1];
    const float* emb1 = (const float*)d_in[2];
    const float* emb2 = (const float*)d_in[3];
    const float* W1   = (const float*)d_in[4];
    const float* b1   = (const float*)d_in[5];
    const float* g1   = (const float*)d_in[6];
    const float* be1  = (const float*)d_in[7];
    const float* W2   = (const float*)d_in[8];
    const float* b2   = (const float*)d_in[9];
    const float* g2   = (const float*)d_in[10];
    const float* be2  = (const float*)d_in[11];
    const float* bias = (const float*)d_in[12];
    float* out = (float*)d_out;

    __nv_bfloat16 *A1h, *A1l, *Z1h, *Z1l, *W1h, *W1l, *W2h, *W2l;
    float *Z2, *stats, *coef, *c2;
    cudaGetSymbolAddress((void**)&A1h, g_A1h);
    cudaGetSymbolAddress((void**)&A1l, g_A1l);
    cudaGetSymbolAddress((void**)&Z1h, g_Z1h);
    cudaGetSymbolAddress((void**)&Z1l, g_Z1l);
    cudaGetSymbolAddress((void**)&W1h, g_W1h);
    cudaGetSymbolAddress((void**)&W1l, g_W1l);
    cudaGetSymbolAddress((void**)&W2h, g_W2h);
    cudaGetSymbolAddress((void**)&W2l, g_W2l);
    cudaGetSymbolAddress((void**)&Z2,  g_Z2);
    cudaGetSymbolAddress((void**)&stats, g_stats);
    cudaGetSymbolAddress((void**)&coef,  g_coef);
    cudaGetSymbolAddress((void**)&c2,    g_c2);

    const int SMEM_BYTES = 3 * 16640 * 2;   // 99840
    cudaFuncSetAttribute(hmma_gemm_kernel<0>,
                         cudaFuncAttributeMaxDynamicSharedMemorySize, SMEM_BYTES);
    cudaFuncSetAttribute(hmma_gemm_kernel<1>,
                         cudaFuncAttributeMaxDynamicSharedMemorySize, SMEM_BYTES);

    zero_kernel<<<(4 * NH + 255) / 256, 256>>>(stats);
    embed_kernel<<<N_ROWS, 640>>>(xi, xv, emb1, emb2, bias, A1h, A1l, out);
    repackW_kernel<<<((size_t)NH * KP1 + 255) / 256, 256>>>(W1, W1h, W1l, ND, KP1);

    dim3 ggrid(5, N_ROWS / 128);
    hmma_gemm_kernel<0><<<ggrid, 256, SMEM_BYTES>>>(
        A1h, A1l, W1h, W1l, b1, Z1h, Z1l, nullptr,
        stats, stats + NH, KP1, NC1);

    prep1_kernel<<<2, 256>>>(stats, g1, be1, coef);
    repackW2c_kernel<<<NH, 128>>>(W2, b2, coef, W2h, W2l, c2);

    hmma_gemm_kernel<1><<<ggrid, 256, SMEM_BYTES>>>(
        Z1h, Z1l, W2h, W2l, c2, nullptr, nullptr, Z2,
        stats + 2 * NH, stats + 3 * NH, KP2, NC2);

    prep2_kernel<<<1, 512>>>(stats, g2, be2, coef);
    rowdot_kernel<<<N_ROWS / 8, 256>>>(Z2, coef, out);
}

// round 6
// speedup vs baseline: 1.8245x; 1.0498x over previous
#include <cuda_runtime.h>
#include <cuda_bf16.h>
#include <cstdint>
#include <math.h>

#define N_ROWS 16384
#define NF     39
#define VP1    100001
#define NE     16
#define ND     624   // F*E
#define NH     400
#define EPS    1e-5f

#define KP1 640   // ND padded to multiple of 32
#define NC1 20    // KP1/32
#define KP2 448   // NH padded to multiple of 32
#define NC2 14    // KP2/32

// ---------------- scratch (static __device__, no allocations) ----------------
__device__ __align__(16) __nv_bfloat16 g_A1h[(size_t)N_ROWS * KP1];
__device__ __align__(16) __nv_bfloat16 g_A1l[(size_t)N_ROWS * KP1];
__device__ __align__(16) __nv_bfloat16 g_Z1h[(size_t)N_ROWS * KP2];
__device__ __align__(16) __nv_bfloat16 g_Z1l[(size_t)N_ROWS * KP2];
__device__ __align__(16) __nv_bfloat16 g_W1h[(size_t)NH * KP1];
__device__ __align__(16) __nv_bfloat16 g_W1l[(size_t)NH * KP1];
__device__ __align__(16) __nv_bfloat16 g_W2h[(size_t)NH * KP2];
__device__ __align__(16) __nv_bfloat16 g_W2l[(size_t)NH * KP2];
__device__ __align__(16) float g_Z2[(size_t)N_ROWS * NH];
__device__ float g_stats[4 * NH];
__device__ float g_coef [3 * NH + 1];  // a1[400], b1fold[400], a2[400], C
__device__ float g_c2   [NH];

// ---------------- helpers ----------------
__device__ __forceinline__ uint32_t smem_u32(const void* p) {
    uint32_t a;
    asm("{ .reg .u64 t; cvta.to.shared.u64 t, %1; cvt.u32.u64 %0, t; }"
        : "=r"(a) : "l"(p));
    return a;
}

__device__ __forceinline__ void cpa16(uint32_t dst, const void* src) {
    asm volatile("cp.async.cg.shared.global [%0], [%1], 16;"
                 :: "r"(dst), "l"(src));
}

#define CP_COMMIT() asm volatile("cp.async.commit_group;" ::: "memory")
#define CP_WAIT1()  asm volatile("cp.async.wait_group 1;" ::: "memory")
#define CP_WAIT0()  asm volatile("cp.async.wait_group 0;" ::: "memory")

#define LDSM_X4(r, addr) \
    asm volatile("ldmatrix.sync.aligned.m8n8.x4.shared.b16 {%0,%1,%2,%3}, [%4];" \
        : "=r"((r)[0]), "=r"((r)[1]), "=r"((r)[2]), "=r"((r)[3]) : "r"(addr))

#define MMA16816(d, a, b0, b1) \
    asm volatile("mma.sync.aligned.m16n8k16.row.col.f32.bf16.bf16.f32 " \
        "{%0,%1,%2,%3}, {%4,%5,%6,%7}, {%8,%9}, {%0,%1,%2,%3};" \
        : "+f"((d)[0]), "+f"((d)[1]), "+f"((d)[2]), "+f"((d)[3]) \
        : "r"((a)[0]), "r"((a)[1]), "r"((a)[2]), "r"((a)[3]), \
          "r"(b0), "r"(b1))

__device__ __forceinline__ void split_bf16(float x, __nv_bfloat16& h, __nv_bfloat16& l) {
    h = __float2bfloat16(x);
    l = __float2bfloat16(x - __bfloat162float(h));
}

// ---------------- zero stats ----------------
__global__ void zero_kernel(float* stats) {
    int i = blockIdx.x * blockDim.x + threadIdx.x;
    if (i < 4 * NH) stats[i] = 0.f;
}

// ---------------- embedding gather + e1 + FM2 + split deep ----------------
__global__ void __launch_bounds__(640) embed_kernel(
    const int* __restrict__ xi, const float* __restrict__ xv,
    const float* __restrict__ emb1, const float* __restrict__ emb2,
    const float* __restrict__ bias,
    __nv_bfloat16* __restrict__ Ah, __nv_bfloat16* __restrict__ Al,
    float* __restrict__ out)
{
    int n = blockIdx.x;
    int t = threadIdx.x;
    __shared__ int   idx_s[NF];
    __shared__ float xv_s[NF];
    __shared__ float vals[ND];
    __shared__ float e1s[NF];
    __shared__ float fm2s[NE];

    if (t < NF) {
        idx_s[t] = xi[n * NF + t];
        xv_s[t]  = xv[n * NF + t];
    }
    __syncthreads();

    if (t < KP1) {
        float v = 0.f;
        if (t < ND) {
            int f = t >> 4, e = t & 15;
            size_t off = ((size_t)f * VP1 + idx_s[f]) * NE + e;
            v = emb2[off] * xv_s[f];
            vals[t] = v;
        }
        __nv_bfloat16 h, l; split_bf16(v, h, l);
        Ah[(size_t)n * KP1 + t] = h;
        Al[(size_t)n * KP1 + t] = l;
    }
    if (t < NF) e1s[t] = emb1[(size_t)t * VP1 + idx_s[t]] * xv_s[t];
    __syncthreads();

    if (t < NE) {
        float s = 0.f, sq = 0.f;
        #pragma unroll
        for (int f = 0; f < NF; f++) {
            float v = vals[f * NE + t];
            s += v; sq += v * v;
        }
        fm2s[t] = 0.5f * (s * s - sq);
    }
    __syncthreads();

    if (t == 0) {
        float tot = bias[0];
        #pragma unroll
        for (int i = 0; i < NF; i++) tot += e1s[i];
        #pragma unroll
        for (int i = 0; i < NE; i++) tot += fm2s[i];
        out[n] = tot;
    }
}

// ---------------- W1 repack: transpose + split ----------------
__global__ void repackW_kernel(const float* __restrict__ W,
                               __nv_bfloat16* __restrict__ Wh,
                               __nv_bfloat16* __restrict__ Wl,
                               int K, int Kpad)
{
    size_t idx = (size_t)blockIdx.x * blockDim.x + threadIdx.x;
    if (idx >= (size_t)NH * Kpad) return;
    int k = (int)(idx % Kpad);
    int n = (int)(idx / Kpad);
    float v = (k < K) ? W[(size_t)k * NH + n] : 0.f;
    __nv_bfloat16 h, l; split_bf16(v, h, l);
    Wh[idx] = h; Wl[idx] = l;
}

// ---------------- BN1 fold ----------------
__global__ void prep1_kernel(const float* __restrict__ stats,
                             const float* __restrict__ g1,
                             const float* __restrict__ be1,
                             float* __restrict__ coef)
{
    int j = blockIdx.x * blockDim.x + threadIdx.x;
    if (j < NH) {
        float mean = stats[j] * (1.f / N_ROWS);
        float var  = stats[NH + j] * (1.f / N_ROWS) - mean * mean;
        float a = g1[j] * rsqrtf(var + EPS);
        coef[j]      = a;                 // scale
        coef[NH + j] = be1[j] - a * mean; // shift
    }
}

// ---------------- W2 repack with BN1 scale folded in, plus c2 vector ----------
__global__ void __launch_bounds__(128) repackW2c_kernel(
    const float* __restrict__ W2, const float* __restrict__ b2,
    const float* __restrict__ coef,
    __nv_bfloat16* __restrict__ Wh, __nv_bfloat16* __restrict__ Wl,
    float* __restrict__ c2)
{
    int n = blockIdx.x;
    int t = threadIdx.x;
    float partial = 0.f;
    for (int k = t; k < KP2; k += 128) {
        float w = 0.f, a = 0.f, sh = 0.f;
        if (k < NH) {
            w  = W2[(size_t)k * NH + n];
            a  = coef[k];
            sh = coef[NH + k];
        }
        __nv_bfloat16 h, l; split_bf16(a * w, h, l);
        Wh[(size_t)n * KP2 + k] = h;
        Wl[(size_t)n * KP2 + k] = l;
        partial += sh * w;
    }
    __shared__ float red[128];
    red[t] = partial;
    __syncthreads();
    for (int s = 64; s > 0; s >>= 1) {
        if (t < s) red[t] += red[t + s];
        __syncthreads();
    }
    if (t == 0) c2[n] = red[0] + b2[n];
}

// ---------------- HMMA GEMM: C = (Ah+Al) @ (Bh+Bl)^T + bias ------------------
// BM=128, BN=80, BK=32; 256 threads = 8 warps; warp tile 16x80.
// 2-stage cp.async pipeline (66.5KB SMEM -> 3 CTAs/SM).
template<int EPI>
__global__ void __launch_bounds__(256, 3) hmma_gemm_kernel(
    const __nv_bfloat16* __restrict__ Ah, const __nv_bfloat16* __restrict__ Al,
    const __nv_bfloat16* __restrict__ Bh, const __nv_bfloat16* __restrict__ Bl,
    const float* __restrict__ bias,
    __nv_bfloat16* __restrict__ Zh, __nv_bfloat16* __restrict__ Zl,
    float* __restrict__ Zf,
    float* __restrict__ gsum, float* __restrict__ gsq,
    int Kpad, int nchunk)
{
    extern __shared__ __nv_bfloat16 smem[];
    const int BUF = 16640;                      // bf16 per buffer
    const uint32_t sbase = smem_u32(smem);

    int tid = threadIdx.x;
    int wid = tid >> 5, lane = tid & 31;
    int n0 = blockIdx.x * 80;
    int m0 = blockIdx.y * 128;

    float acc[10][4];
    #pragma unroll
    for (int i = 0; i < 10; i++)
        #pragma unroll
        for (int j = 0; j < 4; j++) acc[i][j] = 0.f;

    // precomputed per-lane SMEM byte offsets (relative to buffer base)
    const uint32_t aoff = (uint32_t)((wid * 16 + (lane & 15)) * 40
                                     + (lane >> 4) * 8) * 2;
    const int rowB = (lane & 7) + ((lane >> 3) & 1) * 8;
    const uint32_t boff = (uint32_t)(10240 + rowB * 40 + (lane >> 4) * 8) * 2;

    auto load_chunk = [&](int buf, int kc) {
        uint32_t sb = sbase + (uint32_t)buf * BUF * 2;
        int k0 = kc * 32;
        #pragma unroll
        for (int l = 0; l < 2; l++) {
            int i = tid + l * 256;
            int row = i >> 2, c = (i & 3) * 8;
            size_t go = (size_t)(m0 + row) * Kpad + k0 + c;
            uint32_t d = sb + (uint32_t)(row * 40 + c) * 2;
            cpa16(d, Ah + go);
            cpa16(d + 5120 * 2, Al + go);
        }
        #pragma unroll
        for (int l = 0; l < 2; l++) {
            int i = tid + l * 256;
            if (i < 320) {
                int row = i >> 2, c = (i & 3) * 8;
                size_t go = (size_t)(n0 + row) * Kpad + k0 + c;
                uint32_t d = sb + (uint32_t)(10240 + row * 40 + c) * 2;
                cpa16(d, Bh + go);
                cpa16(d + 3200 * 2, Bl + go);
            }
        }
        CP_COMMIT();
    };

    load_chunk(0, 0);
    if (nchunk > 1) load_chunk(1, 1);

    for (int kc = 0; kc < nchunk; kc++) {
        if (kc + 1 < nchunk) CP_WAIT1(); else CP_WAIT0();
        __syncthreads();

        uint32_t sb = sbase + (uint32_t)(kc & 1) * BUF * 2;
        #pragma unroll
        for (int ks = 0; ks < 2; ks++) {
            uint32_t kso = (uint32_t)(ks * 16 * 2);
            uint32_t ah[4], al[4];
            LDSM_X4(ah, sb + aoff + kso);
            LDSM_X4(al, sb + aoff + kso + 5120 * 2);

            uint32_t bbase = sb + boff + kso;
            uint32_t bh[5][4];
            #pragma unroll
            for (int g = 0; g < 5; g++)
                LDSM_X4(bh[g], bbase + (uint32_t)(g * 16 * 40) * 2);
            #pragma unroll
            for (int g = 0; g < 5; g++) {
                MMA16816(acc[2 * g],     ah, bh[g][0], bh[g][2]);
                MMA16816(acc[2 * g + 1], ah, bh[g][1], bh[g][3]);
            }
            #pragma unroll
            for (int g = 0; g < 5; g++) {
                MMA16816(acc[2 * g],     al, bh[g][0], bh[g][2]);
                MMA16816(acc[2 * g + 1], al, bh[g][1], bh[g][3]);
            }
            uint32_t bl[5][4];
            #pragma unroll
            for (int g = 0; g < 5; g++)
                LDSM_X4(bl[g], bbase + (uint32_t)(3200 + g * 16 * 40) * 2);
            #pragma unroll
            for (int g = 0; g < 5; g++) {
                MMA16816(acc[2 * g],     ah, bl[g][0], bl[g][2]);
                MMA16816(acc[2 * g + 1], ah, bl[g][1], bl[g][3]);
            }
        }

        if (kc + 2 < nchunk) {
            __syncthreads();
            load_chunk(kc & 1, kc + 2);
        }
    }

    // ---- epilogue ----
    __syncthreads();
    float* ssum = reinterpret_cast<float*>(smem);       // 80
    float* ssq  = ssum + 80;                            // 80
    for (int i = tid; i < 160; i += 256) ssum[i] = 0.f;
    __syncthreads();

    int r0 = m0 + wid * 16 + (lane >> 2);
    int cb = n0 + (lane & 3) * 2;
    #pragma unroll
    for (int nt = 0; nt < 10; nt++) {
        int n = cb + nt * 8;
        float bz0 = bias[n], bz1 = bias[n + 1];
        float v00 = acc[nt][0] + bz0, v01 = acc[nt][1] + bz1;
        float v10 = acc[nt][2] + bz0, v11 = acc[nt][3] + bz1;

        if (EPI == 0) {
            __nv_bfloat162 h0, l0, h1, l1;
            split_bf16(v00, h0.x, l0.x); split_bf16(v01, h0.y, l0.y);
            split_bf16(v10, h1.x, l1.x); split_bf16(v11, h1.y, l1.y);
            *reinterpret_cast<__nv_bfloat162*>(Zh + (size_t)r0 * KP2 + n) = h0;
            *reinterpret_cast<__nv_bfloat162*>(Zl + (size_t)r0 * KP2 + n) = l0;
            *reinterpret_cast<__nv_bfloat162*>(Zh + (size_t)(r0 + 8) * KP2 + n) = h1;
            *reinterpret_cast<__nv_bfloat162*>(Zl + (size_t)(r0 + 8) * KP2 + n) = l1;
        } else {
            *reinterpret_cast<float2*>(Zf + (size_t)r0 * NH + n) =
                make_float2(v00, v01);
            *reinterpret_cast<float2*>(Zf + (size_t)(r0 + 8) * NH + n) =
                make_float2(v10, v11);
        }

        float s0 = v00 + v10, q0 = v00 * v00 + v10 * v10;
        float s1 = v01 + v11, q1 = v01 * v01 + v11 * v11;
        #pragma unroll
        for (int off = 16; off >= 4; off >>= 1) {
            s0 += __shfl_down_sync(0xFFFFFFFF, s0, off);
            q0 += __shfl_down_sync(0xFFFFFFFF, q0, off);
            s1 += __shfl_down_sync(0xFFFFFFFF, s1, off);
            q1 += __shfl_down_sync(0xFFFFFFFF, q1, off);
        }
        if (lane < 4) {
            int lc = lane * 2 + nt * 8;
            atomicAdd(&ssum[lc],     s0);
            atomicAdd(&ssum[lc + 1], s1);
            atomicAdd(&ssq[lc],      q0);
            atomicAdd(&ssq[lc + 1],  q1);
        }
    }

    if (EPI == 0 && n0 == 320) {
        for (int i = tid; i < 1536; i += 256) {
            int row = i / 12, q = i % 12;
            size_t off = (size_t)(m0 + row) * KP2 + 400 + q * 4;
            *reinterpret_cast<uint2*>(Zh + off) = make_uint2(0u, 0u);
            *reinterpret_cast<uint2*>(Zl + off) = make_uint2(0u, 0u);
        }
    }

    __syncthreads();
    for (int i = tid; i < 80; i += 256) {
        atomicAdd(&gsum[n0 + i], ssum[i]);
        atomicAdd(&gsq[n0 + i],  ssq[i]);
    }
}

// ---------------- BN2 fold ----------------
__global__ void prep2_kernel(const float* __restrict__ stats,
                             const float* __restrict__ g2,
                             const float* __restrict__ be2,
                             float* __restrict__ coef)
{
    int j = threadIdx.x;
    float c = 0.f;
    if (j < NH) {
        float mean = stats[2 * NH + j] * (1.f / N_ROWS);
        float var  = stats[3 * NH + j] * (1.f / N_ROWS) - mean * mean;
        float a = g2[j] * rsqrtf(var + EPS);
        coef[2 * NH + j] = a;
        c = be2[j] - a * mean;
    }
    __shared__ float sh[512];
    sh[j] = c;
    __syncthreads();
    for (int s = 256; s > 0; s >>= 1) {
        if (j < s) sh[j] += sh[j + s];
        __syncthreads();
    }
    if (j == 0) coef[3 * NH] = sh[0];
}

// ---------------- final weighted row-sum ----------------
__global__ void __launch_bounds__(256) rowdot_kernel(
    const float* __restrict__ Z2, const float* __restrict__ coef,
    float* __restrict__ out)
{
    __shared__ float a_s[NH];
    __shared__ float Cs;
    int t = threadIdx.x;
    for (int j = t; j < NH; j += 256) a_s[j] = coef[2 * NH + j];
    if (t == 0) Cs = coef[3 * NH];
    __syncthreads();

    int lane = t & 31, w = t >> 5;
    int row = blockIdx.x * 8 + w;
    float acc = 0.f;
    for (int j = lane; j < NH; j += 32)
        acc += a_s[j] * Z2[(size_t)row * NH + j];
    #pragma unroll
    for (int off = 16; off > 0; off >>= 1)
        acc += __shfl_down_sync(0xFFFFFFFF, acc, off);
    if (lane == 0)
        out[row] += acc + Cs;
}

// ---------------- launch ----------------
extern "C" void kernel_launch(void* const* d_in, const int* in_sizes, int n_in,
                              void* d_out, int out_size)
{
    const int*   xi   = (const int*)  d_in[0];
    const float* xv   = (const float*)d_in[1];
    const float* emb1 = (const float*)d_in[2];
    const float* emb2 = (const float*)d_in[3];
    const float* W1   = (const float*)d_in[4];
    const float* b1   = (const float*)d_in[5];
    const float* g1   = (const float*)d_in[6];
    const float* be1  = (const float*)d_in[7];
    const float* W2   = (const float*)d_in[8];
    const float* b2   = (const float*)d_in[9];
    const float* g2   = (const float*)d_in[10];
    const float* be2  = (const float*)d_in[11];
    const float* bias = (const float*)d_in[12];
    float* out = (float*)d_out;

    __nv_bfloat16 *A1h, *A1l, *Z1h, *Z1l, *W1h, *W1l, *W2h, *W2l;
    float *Z2, *stats, *coef, *c2;
    cudaGetSymbolAddress((void**)&A1h, g_A1h);
    cudaGetSymbolAddress((void**)&A1l, g_A1l);
    cudaGetSymbolAddress((void**)&Z1h, g_Z1h);
    cudaGetSymbolAddress((void**)&Z1l, g_Z1l);
    cudaGetSymbolAddress((void**)&W1h, g_W1h);
    cudaGetSymbolAddress((void**)&W1l, g_W1l);
    cudaGetSymbolAddress((void**)&W2h, g_W2h);
    cudaGetSymbolAddress((void**)&W2l, g_W2l);
    cudaGetSymbolAddress((void**)&Z2,  g_Z2);
    cudaGetSymbolAddress((void**)&stats, g_stats);
    cudaGetSymbolAddress((void**)&coef,  g_coef);
    cudaGetSymbolAddress((void**)&c2,    g_c2);

    const int SMEM_BYTES = 2 * 16640 * 2;   // 66560
    cudaFuncSetAttribute(hmma_gemm_kernel<0>,
                         cudaFuncAttributeMaxDynamicSharedMemorySize, SMEM_BYTES);
    cudaFuncSetAttribute(hmma_gemm_kernel<1>,
                         cudaFuncAttributeMaxDynamicSharedMemorySize, SMEM_BYTES);

    zero_kernel<<<(4 * NH + 255) / 256, 256>>>(stats);
    embed_kernel<<<N_ROWS, 640>>>(xi, xv, emb1, emb2, bias, A1h, A1l, out);
    repackW_kernel<<<((size_t)NH * KP1 + 255) / 256, 256>>>(W1, W1h, W1l, ND, KP1);

    dim3 ggrid(5, N_ROWS / 128);
    hmma_gemm_kernel<0><<<ggrid, 256, SMEM_BYTES>>>(
        A1h, A1l, W1h, W1l, b1, Z1h, Z1l, nullptr,
        stats, stats + NH, KP1, NC1);

    prep1_kernel<<<2, 256>>>(stats, g1, be1, coef);
    repackW2c_kernel<<<NH, 128>>>(W2, b2, coef, W2h, W2l, c2);

    hmma_gemm_kernel<1><<<ggrid, 256, SMEM_BYTES>>>(
        Z1h, Z1l, W2h, W2l, c2, nullptr, nullptr, Z2,
        stats + 2 * NH, stats + 3 * NH, KP2, NC2);

    prep2_kernel<<<1, 512>>>(stats, g2, be2, coef);
    rowdot_kernel<<<N_ROWS / 8, 256>>>(Z2, coef, out);
}